// round 7
// baseline (speedup 1.0000x reference)
#include <cuda_runtime.h>
#include <math.h>
#include <stdint.h>

#define Bq   8
#define Nn   20000
#define Ee   320000
#define Ccells 128
#define Dd   64
#define HOPS 4
#define HID  512
#define OUTD 256
#define K1   (HOPS*Dd)      // 256
#define ROWS (Bq*Nn)        // 160000

// ---------------- device scratch (static, no allocation) ----------------
__device__ int   g_idx[Nn];
__device__ float g_init[Nn*Dd];
__device__ float g_hops[HOPS][(size_t)Bq*Nn*Dd];
__device__ float g_x[(size_t)ROWS*HID];
__device__ int   g_deg[ROWS];
__device__ int   g_cursor[ROWS];
__device__ int   g_rowptr[Bq*(Nn+1)];
__device__ int   g_cols[(size_t)Bq*Ee];
__device__ float g_W1r[(size_t)K1*HID];    // [k_blocked][n], tf32-rounded, rows permuted
__device__ float g_W2r[(size_t)HID*OUTD];  // [k][n], tf32-rounded

// ---------------- helpers ----------------
__device__ __forceinline__ float f2tf32(float x) {
    uint32_t u;
    asm("cvt.rna.tf32.f32 %0, %1;" : "=r"(u) : "f"(x));
    return __uint_as_float(u);
}

__device__ __forceinline__ void mma_tf32(float c[4],
    uint32_t a0, uint32_t a1, uint32_t a2, uint32_t a3,
    uint32_t b0, uint32_t b1) {
    asm volatile(
        "mma.sync.aligned.m16n8k8.row.col.f32.tf32.tf32.f32 "
        "{%0,%1,%2,%3}, {%4,%5,%6,%7}, {%8,%9}, {%0,%1,%2,%3};\n"
        : "+f"(c[0]), "+f"(c[1]), "+f"(c[2]), "+f"(c[3])
        : "r"(a0), "r"(a1), "r"(a2), "r"(a3), "r"(b0), "r"(b1));
}

__device__ __forceinline__ void cp16(uint32_t smem_addr, const void* gptr) {
    asm volatile("cp.async.cg.shared.global [%0], [%1], 16;"
                 :: "r"(smem_addr), "l"(gptr) : "memory");
}
__device__ __forceinline__ void cp_commit() {
    asm volatile("cp.async.commit_group;" ::: "memory");
}
template <int N> __device__ __forceinline__ void cp_wait() {
    asm volatile("cp.async.wait_group %0;" :: "n"(N) : "memory");
}
__device__ __forceinline__ uint32_t smem_u32(const void* p) {
    uint32_t a;
    asm("{ .reg .u64 t; cvta.to.shared.u64 t, %1; cvt.u32.u64 %0, t; }" : "=r"(a) : "l"(p));
    return a;
}

// ---------------- argmax over cells -> gene index ----------------
__global__ void k_argmax(const float* __restrict__ poh) {
    int n = blockIdx.x * blockDim.x + threadIdx.x;
    if (n >= Nn) return;
    float best = poh[n]; int bi = 0;
    for (int c = 1; c < Ccells; c++) {
        float v = poh[(size_t)c * Nn + n];
        if (v > best) { best = v; bi = c; }
    }
    g_idx[n] = bi;
}

__global__ void k_init_emb(const float* __restrict__ emb) {
    int i = blockIdx.x * blockDim.x + threadIdx.x;
    if (i >= Nn * Dd) return;
    int n = i >> 6, d = i & 63;
    g_init[i] = emb[g_idx[n] * Dd + d];
}

// ---------------- weight prep ----------------
__global__ void k_prepW1(const float* __restrict__ W1) {
    int i = blockIdx.x * blockDim.x + threadIdx.x;
    if (i >= K1 * HID) return;
    int k = i / HID, n = i - k * HID;
    int d = k >> 2, h = k & 3;
    g_W1r[(size_t)(h * 64 + d) * HID + n] = f2tf32(W1[i]);
}
__global__ void k_prepW2(const float* __restrict__ W2) {
    int i = blockIdx.x * blockDim.x + threadIdx.x;
    if (i >= HID * OUTD) return;
    g_W2r[i] = f2tf32(W2[i]);
}

// ---------------- CSR build ----------------
__global__ void k_zero_deg() {
    for (int i = blockIdx.x * blockDim.x + threadIdx.x; i < ROWS;
         i += gridDim.x * blockDim.x)
        g_deg[i] = 0;
}

__global__ void k_count(const int* __restrict__ edge) {
    int e = blockIdx.x * blockDim.x + threadIdx.x;
    if (e >= Bq * Ee) return;
    int b = e / Ee, i = e - b * Ee;
    int row = edge[(size_t)b * 2 * Ee + i];
    atomicAdd(&g_deg[b * Nn + row], 1);
}

__global__ void k_scan() {
    __shared__ int part[640];
    int b = blockIdx.x;
    int t = threadIdx.x;
    int base = b * Nn;
    int s = 0;
    for (int i = 0; i < 32; i++) {
        int r = t * 32 + i;
        if (r < Nn) s += g_deg[base + r];
    }
    part[t] = s;
    __syncthreads();
    if (t == 0) {
        int run = 0;
        for (int i = 0; i < 640; i++) { int x = part[i]; part[i] = run; run += x; }
        g_rowptr[b * (Nn + 1) + Nn] = run;
    }
    __syncthreads();
    int off = part[t];
    for (int i = 0; i < 32; i++) {
        int r = t * 32 + i;
        if (r < Nn) {
            g_rowptr[b * (Nn + 1) + r] = off;
            g_cursor[base + r] = off;
            off += g_deg[base + r];
        }
    }
}

__global__ void k_scatter(const int* __restrict__ edge) {
    int e = blockIdx.x * blockDim.x + threadIdx.x;
    if (e >= Bq * Ee) return;
    int b = e / Ee, i = e - b * Ee;
    int row = edge[(size_t)b * 2 * Ee + i];
    int col = edge[(size_t)b * 2 * Ee + Ee + i];
    int pos = atomicAdd(&g_cursor[b * Nn + row], 1);
    g_cols[(size_t)b * Ee + pos] = col;
}

// -------- SPMM gather: half-warp (16 lanes x float4) per edge, 2 edges/iter ----
// Output written tf32-rounded (feeds GEMM1 A raw, and next hop).
__global__ void k_spmm(int hop) {
    int w = blockIdx.x * (blockDim.x >> 5) + (threadIdx.x >> 5);
    if (w >= ROWS) return;
    int lane = threadIdx.x & 31;
    int hw   = lane >> 4;
    int l4   = lane & 15;
    int b = w / Nn, n = w - b * Nn;
    int s = g_rowptr[b * (Nn + 1) + n];
    int e = g_rowptr[b * (Nn + 1) + n + 1];
    const float4* __restrict__ src =
        (hop == 0) ? (const float4*)g_init : (const float4*)g_hops[hop - 1];
    size_t grow = (hop == 0) ? 0 : (size_t)b * Nn;
    const int* __restrict__ cols = &g_cols[(size_t)b * Ee];

    float4 a0 = make_float4(0.f, 0.f, 0.f, 0.f), a1 = a0;
    int j = s + hw;
    for (; j + 2 < e; j += 4) {
        int c0 = cols[j], c1 = cols[j + 2];
        float4 v0 = src[(grow + (size_t)c0) * 16 + l4];
        float4 v1 = src[(grow + (size_t)c1) * 16 + l4];
        a0.x += v0.x; a0.y += v0.y; a0.z += v0.z; a0.w += v0.w;
        a1.x += v1.x; a1.y += v1.y; a1.z += v1.z; a1.w += v1.w;
    }
    if (j < e) {
        float4 v = src[(grow + (size_t)cols[j]) * 16 + l4];
        a0.x += v.x; a0.y += v.y; a0.z += v.z; a0.w += v.w;
    }
    a0.x += a1.x; a0.y += a1.y; a0.z += a1.z; a0.w += a1.w;
    a0.x += __shfl_xor_sync(0xffffffffu, a0.x, 16);
    a0.y += __shfl_xor_sync(0xffffffffu, a0.y, 16);
    a0.z += __shfl_xor_sync(0xffffffffu, a0.z, 16);
    a0.w += __shfl_xor_sync(0xffffffffu, a0.w, 16);
    if (hw == 0) {
        float4 o = make_float4(f2tf32(a0.x), f2tf32(a0.y), f2tf32(a0.z), f2tf32(a0.w));
        ((float4*)g_hops[hop])[(size_t)w * 16 + l4] = o;
    }
}

// ---------------- GEMM1: 128x128 CTA, K-step 16, cp.async pipeline ------------
// A from g_hops (blocked k = h*64+d, tf32-rounded), C -> g_x (f32 + bias)
#define AS_FLOATS (128*20)
#define BS_FLOATS (16*132)
#define NSTAGE 3
#define GEMM_SMEM_BYTES (NSTAGE*(AS_FLOATS + BS_FLOATS)*4)

__global__ void __launch_bounds__(256, 2)
k_gemm1(const float* __restrict__ Wr,
        const float* __restrict__ bias) {
    extern __shared__ float sm[];
    float* Asb = sm;
    float* Bsb = sm + NSTAGE * AS_FLOATS;

    const int tid  = threadIdx.x;
    const int lane = tid & 31;
    const int warp = tid >> 5;
    const int g    = lane >> 2;
    const int tg   = lane & 3;
    const int wm   = warp & 3;
    const int wn   = warp >> 2;
    const int m0w  = wm * 32;
    const int n0w  = wn * 64;

    const int n0 = blockIdx.x * 128;
    const int m0 = blockIdx.y * 128;

    float acc[2][8][4];
    #pragma unroll
    for (int i = 0; i < 2; i++)
        #pragma unroll
        for (int j = 0; j < 8; j++)
            #pragma unroll
            for (int q = 0; q < 4; q++) acc[i][j][q] = 0.f;

    const int am = tid >> 1;
    const int ah = (tid & 1) * 8;
    const int bk = tid >> 4;
    const int bq = (tid & 15) * 8;

    const uint32_t a_sm_base = smem_u32(&Asb[am * 20 + ah]);
    const uint32_t b_sm_base = smem_u32(&Bsb[bk * 132 + bq]);

    auto issue = [&](int kt) {
        const int buf = kt % NSTAGE;
        const int k0 = kt * 16;
        const float* srcA = &g_hops[k0 >> 6][(size_t)(m0 + am) * Dd + (k0 & 63) + ah];
        uint32_t a_sm = a_sm_base + buf * (AS_FLOATS * 4);
        cp16(a_sm, srcA);
        cp16(a_sm + 16, srcA + 4);
        const float* srcB = &Wr[(size_t)(k0 + bk) * HID + n0 + bq];
        uint32_t b_sm = b_sm_base + buf * (BS_FLOATS * 4);
        cp16(b_sm, srcB);
        cp16(b_sm + 16, srcB + 4);
        cp_commit();
    };

    auto compute = [&](int buf) {
        float* Ad = Asb + buf * AS_FLOATS;
        float* Bd = Bsb + buf * BS_FLOATS;
        #pragma unroll
        for (int kk = 0; kk < 16; kk += 8) {
            uint32_t afr[2][4];
            #pragma unroll
            for (int mi = 0; mi < 2; mi++) {
                int mr = m0w + mi * 16 + g;
                afr[mi][0] = __float_as_uint(Ad[mr * 20 + kk + tg]);
                afr[mi][1] = __float_as_uint(Ad[(mr + 8) * 20 + kk + tg]);
                afr[mi][2] = __float_as_uint(Ad[mr * 20 + kk + tg + 4]);
                afr[mi][3] = __float_as_uint(Ad[(mr + 8) * 20 + kk + tg + 4]);
            }
            uint32_t bfr[8][2];
            #pragma unroll
            for (int nf = 0; nf < 8; nf++) {
                int nc = n0w + nf * 8 + g;
                bfr[nf][0] = __float_as_uint(Bd[(kk + tg) * 132 + nc]);
                bfr[nf][1] = __float_as_uint(Bd[(kk + tg + 4) * 132 + nc]);
            }
            #pragma unroll
            for (int mi = 0; mi < 2; mi++)
                #pragma unroll
                for (int nf = 0; nf < 8; nf++)
                    mma_tf32(acc[mi][nf],
                             afr[mi][0], afr[mi][1], afr[mi][2], afr[mi][3],
                             bfr[nf][0], bfr[nf][1]);
        }
    };

    constexpr int NT = K1 / 16;
    issue(0);
    issue(1);
    for (int kt = 0; kt < NT; kt++) {
        if (kt < NT - 1) cp_wait<1>(); else cp_wait<0>();
        __syncthreads();
        if (kt + 2 < NT) issue(kt + 2);
        compute(kt % NSTAGE);
    }

    #pragma unroll
    for (int mi = 0; mi < 2; mi++) {
        #pragma unroll
        for (int nf = 0; nf < 8; nf++) {
            int n = n0 + n0w + nf * 8 + 2 * tg;
            float bv0 = bias[n], bv1 = bias[n + 1];
            size_t mA = (size_t)(m0 + m0w + mi * 16 + g);
            size_t mB = mA + 8;
            float2 r0 = make_float2(acc[mi][nf][0] + bv0, acc[mi][nf][1] + bv1);
            float2 r1 = make_float2(acc[mi][nf][2] + bv0, acc[mi][nf][3] + bv1);
            *(float2*)&g_x[mA * HID + n] = r0;
            *(float2*)&g_x[mB * HID + n] = r1;
        }
    }
}

// -------- GEMM2 fused: LN + GELU + (y @ W2 + b2), CTA 128x256, 512 threads ----
// Phase 1: per-row mean/rstd over HID, gamma/beta -> smem (warms L2).
// Phase 2: K-loop; A staged via LDG->LN->GELU->tf32->STS; B via cp.async (3 st).
#define A2_FLOATS (128*20)
#define B2_FLOATS (16*260)
#define G2_SMEM_BYTES ((2*A2_FLOATS + 3*B2_FLOATS + 256 + 1024)*4)

__global__ void __launch_bounds__(512, 1)
k_gemm2f(const float* __restrict__ Wr,
         const float* __restrict__ gamma,
         const float* __restrict__ beta,
         const float* __restrict__ bias,
         float* __restrict__ out) {
    extern __shared__ float sm[];
    float* Asb  = sm;                       // 2 x [128][20]
    float* Bsb  = sm + 2 * A2_FLOATS;       // 3 x [16][260]
    float* smu  = Bsb + 3 * B2_FLOATS;      // [128]
    float* srs  = smu + 128;                // [128]
    float* sgam = srs + 128;                // [512]
    float* sbet = sgam + 512;               // [512]

    const int tid  = threadIdx.x;
    const int lane = tid & 31;
    const int warp = tid >> 5;          // 0..15
    const int g    = lane >> 2;
    const int tg   = lane & 3;
    const int wm   = warp & 3;
    const int wn   = warp >> 2;         // 0..3
    const int m0w  = wm * 32;
    const int n0w  = wn * 64;
    const int m0   = blockIdx.x * 128;

    const int arow = tid >> 2;          // 0..127
    const int ac4  = (tid & 3) * 4;     // 0,4,8,12

    // ---- phase 1: row stats + gamma/beta preload ----
    {
        const float* xr = &g_x[(size_t)(m0 + arow) * HID + (tid & 3) * 128];
        float s = 0.f, ss = 0.f;
        #pragma unroll
        for (int i = 0; i < 128; i += 4) {
            float4 v = *(const float4*)(xr + i);
            s  += v.x + v.y + v.z + v.w;
            ss += v.x * v.x + v.y * v.y + v.z * v.z + v.w * v.w;
        }
        s  += __shfl_xor_sync(0xffffffffu, s, 1);
        ss += __shfl_xor_sync(0xffffffffu, ss, 1);
        s  += __shfl_xor_sync(0xffffffffu, s, 2);
        ss += __shfl_xor_sync(0xffffffffu, ss, 2);
        if ((tid & 3) == 0) {
            float mu = s * (1.f / HID);
            smu[arow] = mu;
            srs[arow] = rsqrtf(ss * (1.f / HID) - mu * mu + 1e-5f);
        }
        if (tid < 128) {
            *(float4*)&sgam[tid * 4] = *(const float4*)&gamma[tid * 4];
            *(float4*)&sbet[tid * 4] = *(const float4*)&beta[tid * 4];
        }
    }
    __syncthreads();

    float acc[2][8][4];
    #pragma unroll
    for (int i = 0; i < 2; i++)
        #pragma unroll
        for (int j = 0; j < 8; j++)
            #pragma unroll
            for (int q = 0; q < 4; q++) acc[i][j][q] = 0.f;

    const int bk = tid >> 5;            // 0..15
    const int bq = lane * 8;            // 0..248
    const uint32_t b_sm_base = smem_u32(&Bsb[bk * 260 + bq]);

    float4 arg;
    auto ldA = [&](int kt) {
        arg = *(const float4*)&g_x[(size_t)(m0 + arow) * HID + kt * 16 + ac4];
    };
    auto stageA = [&](int kt, int buf) {
        float mu = smu[arow], rs = srs[arow];
        int kb = kt * 16 + ac4;
        float o[4] = {arg.x, arg.y, arg.z, arg.w};
        #pragma unroll
        for (int j = 0; j < 4; j++) {
            float t = (o[j] - mu) * rs * sgam[kb + j] + sbet[kb + j];
            o[j] = f2tf32(t * normcdff(t));
        }
        *(float4*)&Asb[buf * A2_FLOATS + arow * 20 + ac4] =
            make_float4(o[0], o[1], o[2], o[3]);
    };
    auto issueB = [&](int kt) {
        int buf = kt % 3;
        const float* src = &Wr[(size_t)(kt * 16 + bk) * OUTD + bq];
        uint32_t b_sm = b_sm_base + buf * (B2_FLOATS * 4);
        cp16(b_sm, src);
        cp16(b_sm + 16, src + 4);
        cp_commit();
    };
    auto compute = [&](int bufA, int bufB) {
        float* Ad = Asb + bufA * A2_FLOATS;
        float* Bd = Bsb + bufB * B2_FLOATS;
        #pragma unroll
        for (int kk = 0; kk < 16; kk += 8) {
            uint32_t afr[2][4];
            #pragma unroll
            for (int mi = 0; mi < 2; mi++) {
                int mr = m0w + mi * 16 + g;
                afr[mi][0] = __float_as_uint(Ad[mr * 20 + kk + tg]);
                afr[mi][1] = __float_as_uint(Ad[(mr + 8) * 20 + kk + tg]);
                afr[mi][2] = __float_as_uint(Ad[mr * 20 + kk + tg + 4]);
                afr[mi][3] = __float_as_uint(Ad[(mr + 8) * 20 + kk + tg + 4]);
            }
            uint32_t bfr[8][2];
            #pragma unroll
            for (int nf = 0; nf < 8; nf++) {
                int nc = n0w + nf * 8 + g;
                bfr[nf][0] = __float_as_uint(Bd[(kk + tg) * 260 + nc]);
                bfr[nf][1] = __float_as_uint(Bd[(kk + tg + 4) * 260 + nc]);
            }
            #pragma unroll
            for (int mi = 0; mi < 2; mi++)
                #pragma unroll
                for (int nf = 0; nf < 8; nf++)
                    mma_tf32(acc[mi][nf],
                             afr[mi][0], afr[mi][1], afr[mi][2], afr[mi][3],
                             bfr[nf][0], bfr[nf][1]);
        }
    };

    constexpr int NT = HID / 16;   // 32
    ldA(0);
    issueB(0);
    issueB(1);
    for (int kt = 0; kt < NT; kt++) {
        stageA(kt, kt & 1);
        if (kt < NT - 1) cp_wait<1>(); else cp_wait<0>();
        __syncthreads();
        if (kt + 1 < NT) ldA(kt + 1);
        if (kt + 2 < NT) issueB(kt + 2);
        compute(kt & 1, kt % 3);
    }

    // ---- epilogue: bias + store to out ----
    #pragma unroll
    for (int mi = 0; mi < 2; mi++) {
        #pragma unroll
        for (int nf = 0; nf < 8; nf++) {
            int n = n0w + nf * 8 + 2 * tg;
            float bv0 = bias[n], bv1 = bias[n + 1];
            size_t mA = (size_t)(m0 + m0w + mi * 16 + g);
            size_t mB = mA + 8;
            float2 r0 = make_float2(acc[mi][nf][0] + bv0, acc[mi][nf][1] + bv1);
            float2 r1 = make_float2(acc[mi][nf][2] + bv0, acc[mi][nf][3] + bv1);
            *(float2*)&out[mA * OUTD + n] = r0;
            *(float2*)&out[mB * OUTD + n] = r1;
        }
    }
}

// ---------------- launch ----------------
extern "C" void kernel_launch(void* const* d_in, const int* in_sizes, int n_in,
                              void* d_out, int out_size) {
    int p = 0;
    auto pick = [&]() -> const void* {
        while (p < n_in && in_sizes[p] <= 1) p++;
        return d_in[p++];
    };
    const int*   edge  = (const int*)  pick();
    const float* poh   = (const float*)pick();
    const float* emb   = (const float*)pick();
    const float* W1    = (const float*)pick();
    const float* b1    = (const float*)pick();
    const float* gamma = (const float*)pick();
    const float* beta  = (const float*)pick();
    const float* W2    = (const float*)pick();
    const float* b2    = (const float*)pick();
    float* out = (float*)d_out;

    cudaFuncSetAttribute(k_gemm1,
                         cudaFuncAttributeMaxDynamicSharedMemorySize, GEMM_SMEM_BYTES);
    cudaFuncSetAttribute(k_gemm2f,
                         cudaFuncAttributeMaxDynamicSharedMemorySize, G2_SMEM_BYTES);

    k_argmax<<<(Nn + 255) / 256, 256>>>(poh);
    k_init_emb<<<(Nn * Dd + 255) / 256, 256>>>(emb);

    k_prepW1<<<(K1 * HID + 255) / 256, 256>>>(W1);
    k_prepW2<<<(HID * OUTD + 255) / 256, 256>>>(W2);

    k_zero_deg<<<256, 256>>>();
    k_count<<<(Bq * Ee + 255) / 256, 256>>>(edge);
    k_scan<<<Bq, 640>>>();
    k_scatter<<<(Bq * Ee + 255) / 256, 256>>>(edge);

    for (int h = 0; h < HOPS; h++)
        k_spmm<<<ROWS / 8, 256>>>(h);

    float* w1r; cudaGetSymbolAddress((void**)&w1r, g_W1r);
    float* w2r; cudaGetSymbolAddress((void**)&w2r, g_W2r);

    {
        dim3 grid(HID / 128, ROWS / 128);
        k_gemm1<<<grid, 256, GEMM_SMEM_BYTES>>>(w1r, b1);
    }

    {
        dim3 grid(ROWS / 128);
        k_gemm2f<<<grid, 512, G2_SMEM_BYTES>>>(w2r, gamma, beta, b2, out);
    }
}